// round 3
// baseline (speedup 1.0000x reference)
#include <cuda_runtime.h>
#include <cuda_bf16.h>

#define BATCH   4096
#define INDIM   1024
#define OUTDIM  1024
#define NNZ     52224
#define CAP     128          // max entries per output column (mean ~51)
#define ROWS    32           // batch rows per CTA (= warp width)
#define THREADS 1024         // 32 warps, 32 output columns per warp
#define CPW     32           // cols per warp
#define SSTRIDE 33           // padded smem stride (floats): conflict-free fill + gather

// Device scratch (allocation-free rule: __device__ globals)
__device__ int g_len[OUTDIM];
__device__ int g_lenp[OUTDIM / 2];                   // quads per column-PAIR (common length)
__device__ __align__(16) int   g_ii[OUTDIM * CAP];   // BYTE offsets: ind_in*SSTRIDE*4
__device__ __align__(16) float g_w [OUTDIM * CAP];

// ---------------- preprocessing: bucket NNZ by output column ----------------

__global__ void k_zero() {
    int j = blockIdx.x * blockDim.x + threadIdx.x;
    if (j < OUTDIM) g_len[j] = 0;
}

__global__ void k_fill(const int* __restrict__ ind_in,
                       const int* __restrict__ ind_out,
                       const float* __restrict__ weight) {
    int k = blockIdx.x * blockDim.x + threadIdx.x;
    if (k < NNZ) {
        int j = ind_out[k];
        int p = atomicAdd(&g_len[j], 1);
        if (p < CAP) {
            g_ii[j * CAP + p] = ind_in[k] * (SSTRIDE * 4);   // precomputed byte offset
            g_w [j * CAP + p] = weight[k];
        }
    }
}

// Pad BOTH columns of each pair (2t, 2t+1) to a common multiple-of-4 length
// so the main loop can walk two lists with a single trip count.
__global__ void k_pad() {
    int t = blockIdx.x * blockDim.x + threadIdx.x;
    if (t < OUTDIM / 2) {
        int ja = 2 * t, jb = 2 * t + 1;
        int na = min(g_len[ja], CAP);
        int nb = min(g_len[jb], CAP);
        int L  = (max(na, nb) + 3) & ~3;
        for (int p = na; p < L; ++p) { g_ii[ja * CAP + p] = 0; g_w[ja * CAP + p] = 0.0f; }
        for (int p = nb; p < L; ++p) { g_ii[jb * CAP + p] = 0; g_w[jb * CAP + p] = 0.0f; }
        g_lenp[t] = L >> 2;
    }
}

// ---------------- main kernel: paired-column register accumulation ----------------
//
// CTA = 32 batch rows, 32 warps. Input tile transposed into smem:
// in_s[col*SSTRIDE + row]. Warp owns 32 output columns, processed as 16 PAIRS:
// the inner loop walks both lists together -> 4 independent LDG.128 in flight
// per iteration (vs 2), hiding the ~250cyc L2 latency of the streaming entry
// lists. Gathers from smem are conflict-free; accumulators in registers; no
// atomics anywhere.

__global__ __launch_bounds__(THREADS, 1)
void k_main(const float* __restrict__ input,
            const float* __restrict__ bias,
            float* __restrict__ out) {
    extern __shared__ float in_s[];               // [INDIM][SSTRIDE] floats
    const int tid      = threadIdx.x;
    const int base_row = blockIdx.x * ROWS;

    // Stage transposed input tile (coalesced global reads, conflict-free STS)
    for (int idx = tid; idx < ROWS * INDIM; idx += THREADS) {
        int row = idx >> 10;                      // / INDIM
        int col = idx & (INDIM - 1);
        in_s[col * SSTRIDE + row] = input[(size_t)(base_row + row) * INDIM + col];
    }
    __syncthreads();

    const int warp = tid >> 5;
    const int lane = tid & 31;
    const char* lane_base = (const char*)in_s + lane * 4;
    const int jwarp = warp * CPW;
    float* orow = out + (size_t)(base_row + lane) * OUTDIM;

    #pragma unroll
    for (int b = 0; b < CPW / 8; ++b) {           // 4 batches of 8 columns
        float acc[8];
        #pragma unroll
        for (int pr = 0; pr < 4; ++pr) {          // 4 pairs per batch
            const int j0 = jwarp + b * 8 + pr * 2;
            const int L  = g_lenp[j0 >> 1];
            const int4*   ip0 = (const int4*  )(g_ii +  j0      * CAP);
            const float4* wp0 = (const float4*)(g_w  +  j0      * CAP);
            const int4*   ip1 = (const int4*  )(g_ii + (j0 + 1) * CAP);
            const float4* wp1 = (const float4*)(g_w  + (j0 + 1) * CAP);
            float a0 = 0.0f, a1 = 0.0f, a2 = 0.0f, a3 = 0.0f;
            for (int p = 0; p < L; ++p) {
                int4   i0 = ip0[p];
                float4 w0 = wp0[p];
                int4   i1 = ip1[p];
                float4 w1 = wp1[p];
                a0 += *(const float*)(lane_base + i0.x) * w0.x;
                a2 += *(const float*)(lane_base + i1.x) * w1.x;
                a1 += *(const float*)(lane_base + i0.y) * w0.y;
                a3 += *(const float*)(lane_base + i1.y) * w1.y;
                a0 += *(const float*)(lane_base + i0.z) * w0.z;
                a2 += *(const float*)(lane_base + i1.z) * w1.z;
                a1 += *(const float*)(lane_base + i0.w) * w0.w;
                a3 += *(const float*)(lane_base + i1.w) * w1.w;
            }
            acc[pr * 2]     = a0 + a1 + bias[j0];
            acc[pr * 2 + 1] = a2 + a3 + bias[j0 + 1];
        }
        // Vectorized output: lane writes its row's 8-column chunk as 2x float4
        float* op = orow + jwarp + b * 8;
        *(float4*)(op)     = make_float4(acc[0], acc[1], acc[2], acc[3]);
        *(float4*)(op + 4) = make_float4(acc[4], acc[5], acc[6], acc[7]);
    }
}

// ---------------- launch ----------------

extern "C" void kernel_launch(void* const* d_in, const int* in_sizes, int n_in,
                              void* d_out, int out_size) {
    const float* input   = (const float*)d_in[0];   // [4096,1024] f32
    const float* weight  = (const float*)d_in[1];   // [52224]     f32
    const float* bias    = (const float*)d_in[2];   // [1024]      f32
    const int*   ind_in  = (const int*)  d_in[3];   // [52224]     i32
    const int*   ind_out = (const int*)  d_in[4];   // [52224]     i32
    float*       out     = (float*)d_out;           // [4096,1024] f32

    const int smem_bytes = INDIM * SSTRIDE * (int)sizeof(float);  // 135168
    cudaFuncSetAttribute(k_main, cudaFuncAttributeMaxDynamicSharedMemorySize, smem_bytes);

    k_zero<<<(OUTDIM + 255) / 256, 256>>>();
    k_fill<<<(NNZ + 255) / 256, 256>>>(ind_in, ind_out, weight);
    k_pad <<<(OUTDIM / 2 + 255) / 256, 256>>>();
    k_main<<<BATCH / ROWS, THREADS, smem_bytes>>>(input, bias, out);
}